// round 14
// baseline (speedup 1.0000x reference)
#include <cuda_runtime.h>
#include <cuda_bf16.h>
#include <math.h>

#define BB 2
#define TT 2048
#define DIM 1024
#define HID 4096
#define NH 16
#define KVH 4
#define HD 64
#define WIN 512
#define MROWS (BB*TT)       // 4096
#define QKVN 1536

// ---------------- scratch ----------------
__device__ __nv_bfloat16 g_xnb[MROWS * DIM];
__device__ __nv_bfloat16 g_qkv[MROWS * QKVN];
__device__ __nv_bfloat16 g_qb [BB * NH  * TT * HD];
__device__ __nv_bfloat16 g_kb [BB * KVH * TT * HD];
__device__ __nv_bfloat16 g_vb [BB * KVH * TT * HD];
__device__ __nv_bfloat16 g_yb [MROWS * NH * HD];
__device__ float         g_h  [MROWS * DIM];
__device__ __nv_bfloat16 g_hnb[MROWS * DIM];
__device__ __nv_bfloat16 g_a1 [MROWS * HID];
__device__ __nv_bfloat16 g_gb [MROWS * HID];
__device__ __nv_bfloat16 g_wqkv[QKVN * DIM];
__device__ __nv_bfloat16 g_wob [DIM * NH * HD];
__device__ __nv_bfloat16 g_w1b [HID * DIM];
__device__ __nv_bfloat16 g_w3b [HID * DIM];
__device__ __nv_bfloat16 g_w2b [DIM * HID];

// ---------------- helpers ----------------
__device__ __forceinline__ void cp16(unsigned saddr, const void* g) {
    asm volatile("cp.async.cg.shared.global [%0], [%1], 16;\n" :: "r"(saddr), "l"(g));
}
__device__ __forceinline__ uint4 ldm_x4(unsigned addr) {
    uint4 r;
    asm volatile("ldmatrix.sync.aligned.m8n8.x4.shared.b16 {%0,%1,%2,%3}, [%4];\n"
                 : "=r"(r.x), "=r"(r.y), "=r"(r.z), "=r"(r.w) : "r"(addr));
    return r;
}
__device__ __forceinline__ uint4 ldm_x4t(unsigned addr) {
    uint4 r;
    asm volatile("ldmatrix.sync.aligned.m8n8.x4.trans.shared.b16 {%0,%1,%2,%3}, [%4];\n"
                 : "=r"(r.x), "=r"(r.y), "=r"(r.z), "=r"(r.w) : "r"(addr));
    return r;
}
__device__ __forceinline__ float ex2(float x) {
    float r; asm("ex2.approx.f32 %0, %1;" : "=f"(r) : "f"(x)); return r;
}
__device__ __forceinline__ void mma16816(
    float* c, unsigned a0, unsigned a1, unsigned a2, unsigned a3,
    unsigned b0, unsigned b1)
{
    asm volatile(
        "mma.sync.aligned.m16n8k16.row.col.f32.bf16.bf16.f32 "
        "{%0,%1,%2,%3}, {%4,%5,%6,%7}, {%8,%9}, {%0,%1,%2,%3};"
        : "+f"(c[0]), "+f"(c[1]), "+f"(c[2]), "+f"(c[3])
        : "r"(a0), "r"(a1), "r"(a2), "r"(a3), "r"(b0), "r"(b1));
}

// ---------------- fused weight conversion ----------------
#define R0 ((NH*HD*DIM)/4)
#define R1 (R0 + (KVH*HD*DIM)/4)
#define R2 (R1 + (KVH*HD*DIM)/4)
#define R3 (R2 + (DIM*NH*HD)/4)
#define R4 (R3 + (HID*DIM)/4)
#define R5 (R4 + (HID*DIM)/4)
#define R6 (R5 + (DIM*HID)/4)

__global__ __launch_bounds__(256) void wconv_kernel(
    const float* __restrict__ wq, const float* __restrict__ wk,
    const float* __restrict__ wv, const float* __restrict__ wo,
    const float* __restrict__ w1, const float* __restrict__ w3,
    const float* __restrict__ w2,
    __nv_bfloat16* __restrict__ wqkv, __nv_bfloat16* __restrict__ wob,
    __nv_bfloat16* __restrict__ w1b, __nv_bfloat16* __restrict__ w3b,
    __nv_bfloat16* __restrict__ w2b)
{
    int i = blockIdx.x * 256 + threadIdx.x;
    if (i >= R6) return;
    const float* s; __nv_bfloat16* d; int off;
    if (i < R0)      { s = wq; d = wqkv;                       off = i; }
    else if (i < R1) { s = wk; d = wqkv + NH*HD*DIM;           off = i - R0; }
    else if (i < R2) { s = wv; d = wqkv + (NH+KVH)*HD*DIM;     off = i - R1; }
    else if (i < R3) { s = wo; d = wob;                        off = i - R2; }
    else if (i < R4) { s = w1; d = w1b;                        off = i - R3; }
    else if (i < R5) { s = w3; d = w3b;                        off = i - R4; }
    else             { s = w2; d = w2b;                        off = i - R5; }
    float4 v = ((const float4*)s)[off];
    __nv_bfloat162 lo = __floats2bfloat162_rn(v.x, v.y);
    __nv_bfloat162 hi = __floats2bfloat162_rn(v.z, v.w);
    uint2 r; r.x = *(unsigned*)&lo; r.y = *(unsigned*)&hi;
    ((uint2*)d)[off] = r;
}

// ---------------- RMSNorm over DIM=1024, bf16 out ----------------
__global__ __launch_bounds__(256) void rmsnorm_kernel(
    const float* __restrict__ x, const float* __restrict__ w,
    __nv_bfloat16* __restrict__ out, float eps)
{
    int row = blockIdx.x;
    int tid = threadIdx.x;
    const float4* xr = (const float4*)(x + (size_t)row * DIM);
    float4 xv = xr[tid];
    float acc = xv.x*xv.x + xv.y*xv.y + xv.z*xv.z + xv.w*xv.w;

    __shared__ float red[8];
    #pragma unroll
    for (int o = 16; o > 0; o >>= 1) acc += __shfl_xor_sync(0xffffffffu, acc, o);
    if ((tid & 31) == 0) red[tid >> 5] = acc;
    __syncthreads();
    if (tid < 8) {
        float a = red[tid];
        #pragma unroll
        for (int o = 4; o > 0; o >>= 1) a += __shfl_xor_sync(0xffu, a, o);
        if (tid == 0) red[0] = a;
    }
    __syncthreads();
    float r = rsqrtf(red[0] * (1.0f / DIM) + eps);

    float4 wv = ((const float4*)w)[tid];
    __nv_bfloat162 lo = __floats2bfloat162_rn(xv.x * r * wv.x, xv.y * r * wv.y);
    __nv_bfloat162 hi = __floats2bfloat162_rn(xv.z * r * wv.z, xv.w * r * wv.w);
    uint2 ov; ov.x = *(unsigned*)&lo; ov.y = *(unsigned*)&hi;
    ((uint2*)(out + (size_t)row * DIM))[tid] = ov;
}

// ---------------- fused pack q/k/v ----------------
#define NQVEC (MROWS * NH)
#define NKVEC (MROWS * KVH)
__global__ __launch_bounds__(256) void packall_kernel(
    const __nv_bfloat16* __restrict__ qkv,
    const float* __restrict__ qw, const float* __restrict__ kw,
    __nv_bfloat16* __restrict__ qd, __nv_bfloat16* __restrict__ kd,
    __nv_bfloat16* __restrict__ vd, float qscale)
{
    int vec = blockIdx.x * 8 + (threadIdx.x >> 5);
    int lane = threadIdx.x & 31;

    int mode, idx;
    if (vec < NQVEC)               { mode = 0; idx = vec; }
    else if (vec < NQVEC + NKVEC)  { mode = 1; idx = vec - NQVEC; }
    else                           { mode = 2; idx = vec - NQVEC - NKVEC; }

    int nh = (mode == 0) ? NH : KVH;
    int colOff = (mode == 0) ? 0 : (mode == 1 ? NH * HD : (NH + KVH) * HD);
    int row = idx / nh, hh = idx % nh;
    int b = row / TT, t = row % TT;

    __nv_bfloat162 tv = ((const __nv_bfloat162*)(qkv + (size_t)row * QKVN + colOff + hh * HD))[lane];
    float vx = __bfloat162float(tv.x), vy = __bfloat162float(tv.y);

    float r = 1.0f, sc = 1.0f;
    float wx = 1.f, wy = 1.f;
    if (mode < 2) {
        float acc = vx * vx + vy * vy;
        #pragma unroll
        for (int o = 16; o > 0; o >>= 1) acc += __shfl_xor_sync(0xffffffffu, acc, o);
        r = rsqrtf(acc * (1.0f / HD) + 1e-6f);
        const float* wp = (mode == 0) ? qw : kw;
        float2 wv = ((const float2*)wp)[lane];
        wx = wv.x; wy = wv.y;
        if (mode == 0) sc = qscale;
    }
    __nv_bfloat16* dst = (mode == 0) ? qd : (mode == 1 ? kd : vd);
    __nv_bfloat162 ob = __floats2bfloat162_rn(vx * r * wx * sc, vy * r * wy * sc);
    *(__nv_bfloat162*)(dst + (((size_t)(b * nh + hh) * TT + t) * HD) + lane * 2) = ob;
}

// ---------------- bf16 GEMM: 128x128x64 block, 8 warps (2Mx4N), 64x32 warp tile ----
// 2-stage double buffer, 73.7KB smem -> 2 CTAs/SM
#define STAGES 2
#define KT 64
#define PITCHB 144
#define OPBYTES (128 * PITCHB)
#define STAGE_BYTES (2 * OPBYTES)
#define GSMEM (STAGES * STAGE_BYTES)   // 73728

// EPI 0: fp32 store; 1: fp32 res+scale; 2: bf16 silu(other_bf16)*acc; 3: bf16 store
template <int EPI>
__global__ __launch_bounds__(256, 2) void gemm_kernel(
    const __nv_bfloat16* __restrict__ A, const __nv_bfloat16* __restrict__ W,
    void* __restrict__ Cv, int M, int N, int K,
    const float* __restrict__ res, const float* __restrict__ scale,
    const __nv_bfloat16* __restrict__ other)
{
    extern __shared__ char smem[];
    const int bm = blockIdx.y * 128;
    const int bn = blockIdx.x * 128;
    const int tid = threadIdx.x;
    const int warpId = tid >> 5, lane = tid & 31;
    const int gid = lane >> 2, tg = lane & 3;
    const int warpM = warpId & 1, warpN = warpId >> 1;
    const int r8 = lane & 7;

    const unsigned sbase = (unsigned)__cvta_generic_to_shared(smem);
    const int ktiles = K >> 6;

    float acc[4][4][4];
    #pragma unroll
    for (int mi = 0; mi < 4; mi++)
        #pragma unroll
        for (int ni = 0; ni < 4; ni++)
            #pragma unroll
            for (int c = 0; c < 4; c++) acc[mi][ni][c] = 0.f;

    auto fetch = [&](int s, int kt) {
        unsigned sa = sbase + s * STAGE_BYTES;
        unsigned sb = sa + OPBYTES;
        #pragma unroll
        for (int i = 0; i < 4; i++) {
            int chunk = tid + i * 256;
            int row = chunk >> 3, c = chunk & 7;
            size_t go = (size_t)row * K + (size_t)kt * KT + c * 8;
            cp16(sa + row * PITCHB + c * 16, A + (size_t)bm * K + go);
            cp16(sb + row * PITCHB + c * 16, W + (size_t)bn * K + go);
        }
    };

    unsigned aoff[4], boff[2];
    #pragma unroll
    for (int mi = 0; mi < 4; mi++)
        aoff[mi] = (warpM * 64 + mi * 16 + ((lane >> 3) & 1) * 8 + r8) * PITCHB + (lane >> 4) * 16;
    #pragma unroll
    for (int np = 0; np < 2; np++)
        boff[np] = (warpN * 32 + np * 16 + (lane >> 4) * 8 + r8) * PITCHB + ((lane >> 3) & 1) * 16;

    fetch(0, 0);
    asm volatile("cp.async.commit_group;\n" ::: "memory");

    for (int kt = 0; kt < ktiles; kt++) {
        if (kt + 1 < ktiles) {
            fetch((kt + 1) & 1, kt + 1);
            asm volatile("cp.async.commit_group;\n" ::: "memory");
            asm volatile("cp.async.wait_group 1;\n" ::: "memory");
        } else {
            asm volatile("cp.async.wait_group 0;\n" ::: "memory");
        }
        __syncthreads();

        const unsigned sa = sbase + (kt & 1) * STAGE_BYTES;
        const unsigned sb = sa + OPBYTES;

        #pragma unroll
        for (int ks = 0; ks < 4; ks++) {
            uint4 Af[4], Bf[2];
            #pragma unroll
            for (int mi = 0; mi < 4; mi++) Af[mi] = ldm_x4(sa + aoff[mi] + ks * 32);
            #pragma unroll
            for (int np = 0; np < 2; np++) Bf[np] = ldm_x4(sb + boff[np] + ks * 32);
            #pragma unroll
            for (int mi = 0; mi < 4; mi++) {
                mma16816(acc[mi][0], Af[mi].x, Af[mi].y, Af[mi].z, Af[mi].w, Bf[0].x, Bf[0].y);
                mma16816(acc[mi][1], Af[mi].x, Af[mi].y, Af[mi].z, Af[mi].w, Bf[0].z, Bf[0].w);
                mma16816(acc[mi][2], Af[mi].x, Af[mi].y, Af[mi].z, Af[mi].w, Bf[1].x, Bf[1].y);
                mma16816(acc[mi][3], Af[mi].x, Af[mi].y, Af[mi].z, Af[mi].w, Bf[1].z, Bf[1].w);
            }
        }
        __syncthreads();
    }

    #pragma unroll
    for (int mi = 0; mi < 4; mi++) {
        #pragma unroll
        for (int ni = 0; ni < 4; ni++) {
            int m0 = bm + warpM * 64 + mi * 16 + gid;
            int n0 = bn + warpN * 32 + ni * 8 + tg * 2;
            #pragma unroll
            for (int half = 0; half < 2; half++) {
                int m = m0 + half * 8;
                size_t base = (size_t)m * N + n0;
                float v0 = acc[mi][ni][half * 2 + 0];
                float v1 = acc[mi][ni][half * 2 + 1];
                if (EPI == 0) {
                    float2 ov; ov.x = v0; ov.y = v1;
                    *(float2*)((float*)Cv + base) = ov;
                } else if (EPI == 1) {
                    v0 = res[base + 0] + v0 * scale[n0 + 0];
                    v1 = res[base + 1] + v1 * scale[n0 + 1];
                    float2 ov; ov.x = v0; ov.y = v1;
                    *(float2*)((float*)Cv + base) = ov;
                } else if (EPI == 2) {
                    __nv_bfloat162 ab = *(const __nv_bfloat162*)(other + base);
                    float a0 = __bfloat162float(ab.x);
                    float a1 = __bfloat162float(ab.y);
                    v0 = (a0 / (1.f + __expf(-a0))) * v0;
                    v1 = (a1 / (1.f + __expf(-a1))) * v1;
                    __nv_bfloat162 p = __floats2bfloat162_rn(v0, v1);
                    *(__nv_bfloat162*)((__nv_bfloat16*)Cv + base) = p;
                } else {
                    __nv_bfloat162 p = __floats2bfloat162_rn(v0, v1);
                    *(__nv_bfloat162*)((__nv_bfloat16*)Cv + base) = p;
                }
            }
        }
    }
}

// ---------------- MMA flash attention, sliding window, GQA ----------------
#define ACK 64
#define APITCHB 144
#define AOP (ACK * APITCHB)
#define ASTAGE (2 * AOP)

__global__ __launch_bounds__(256) void fattn_kernel(
    const __nv_bfloat16* __restrict__ qb, const __nv_bfloat16* __restrict__ kb,
    const __nv_bfloat16* __restrict__ vb, __nv_bfloat16* __restrict__ yb)
{
    __shared__ char asmem[2 * ASTAGE];
    const int qt = blockIdx.x, bh = blockIdx.y;
    const int b = bh / NH, h = bh % NH;
    const int kvh = h / (NH / KVH);
    const int tid = threadIdx.x;
    const int w = tid >> 5, lane = tid & 31;
    const int gid = lane >> 2, tg = lane & 3;
    const int r8 = lane & 7;
    const int q0 = qt * 128;
    const int t0 = q0 + w * 16 + gid;
    const int t1 = t0 + 8;

    const unsigned sbase = (unsigned)__cvta_generic_to_shared(asmem);

    const __nv_bfloat16* qbase = qb + (size_t)(b * NH + h) * TT * HD;
    unsigned qa[4][4];
    #pragma unroll
    for (int kt = 0; kt < 4; kt++) {
        qa[kt][0] = *(const unsigned*)(qbase + (size_t)t0 * HD + kt * 16 + 2 * tg);
        qa[kt][1] = *(const unsigned*)(qbase + (size_t)t1 * HD + kt * 16 + 2 * tg);
        qa[kt][2] = *(const unsigned*)(qbase + (size_t)t0 * HD + kt * 16 + 8 + 2 * tg);
        qa[kt][3] = *(const unsigned*)(qbase + (size_t)t1 * HD + kt * 16 + 8 + 2 * tg);
    }

    float oacc[8][4];
    #pragma unroll
    for (int j = 0; j < 8; j++)
        #pragma unroll
        for (int c = 0; c < 4; c++) oacc[j][c] = 0.f;
    float m0 = -1e30f, m1 = -1e30f, l0 = 0.f, l1 = 0.f;

    const int kstart = max(0, q0 - WIN + 1) & ~(ACK - 1);
    const int nch = (q0 + 128 - kstart) / ACK;

    const __nv_bfloat16* kbase = kb + (size_t)(b * KVH + kvh) * TT * HD;
    const __nv_bfloat16* vbase = vb + (size_t)(b * KVH + kvh) * TT * HD;

    auto fetch = [&](int s, int kc) {
        unsigned sk = sbase + s * ASTAGE;
        unsigned sv = sk + AOP;
        #pragma unroll
        for (int i = 0; i < 2; i++) {
            int chunk = tid + i * 256;
            int row = chunk >> 3, c = chunk & 7;
            cp16(sk + row * APITCHB + c * 16, kbase + (size_t)(kc + row) * HD + c * 8);
            cp16(sv + row * APITCHB + c * 16, vbase + (size_t)(kc + row) * HD + c * 8);
        }
    };

    unsigned koff[4], voff0;
    #pragma unroll
    for (int np = 0; np < 4; np++)
        koff[np] = (np * 16 + (lane >> 4) * 8 + r8) * APITCHB + ((lane >> 3) & 1) * 16;
    voff0 = (((lane >> 3) & 1) * 8 + r8) * APITCHB + (lane >> 4) * 16;

    fetch(0, kstart);
    asm volatile("cp.async.commit_group;\n" ::: "memory");

    for (int ci = 0; ci < nch; ci++) {
        int kc = kstart + ci * ACK;
        bool more = (ci + 1 < nch);
        if (more) {
            fetch((ci + 1) & 1, kc + ACK);
            asm volatile("cp.async.commit_group;\n" ::: "memory");
            asm volatile("cp.async.wait_group 1;\n" ::: "memory");
        } else {
            asm volatile("cp.async.wait_group 0;\n" ::: "memory");
        }
        __syncthreads();

        const unsigned sk = sbase + (ci & 1) * ASTAGE;
        const unsigned sv = sk + AOP;

        float s[8][4];
        #pragma unroll
        for (int j = 0; j < 8; j++)
            #pragma unroll
            for (int c = 0; c < 4; c++) s[j][c] = 0.f;
        #pragma unroll
        for (int ks = 0; ks < 4; ks++) {
            #pragma unroll
            for (int np = 0; np < 4; np++) {
                uint4 Bf = ldm_x4(sk + koff[np] + ks * 32);
                mma16816(s[np * 2 + 0], qa[ks][0], qa[ks][1], qa[ks][2], qa[ks][3], Bf.x, Bf.y);
                mma16816(s[np * 2 + 1], qa[ks][0], qa[ks][1], qa[ks][2], qa[ks][3], Bf.z, Bf.w);
            }
        }

        float cmax0 = -INFINITY, cmax1 = -INFINITY;
        #pragma unroll
        for (int j = 0; j < 8; j++) {
            int col = kc + j * 8 + 2 * tg;
            #pragma unroll
            for (int cc = 0; cc < 2; cc++) {
                int c0 = col + cc;
                if (!(c0 <= t0 && (t0 - c0) < WIN)) s[j][cc] = -INFINITY;
                if (!(c0 <= t1 && (t1 - c0) < WIN)) s[j][2 + cc] = -INFINITY;
            }
            cmax0 = fmaxf(cmax0, fmaxf(s[j][0], s[j][1]));
            cmax1 = fmaxf(cmax1, fmaxf(s[j][2], s[j][3]));
        }
        cmax0 = fmaxf(cmax0, __shfl_xor_sync(0xffffffffu, cmax0, 1));
        cmax0 = fmaxf(cmax0, __shfl_xor_sync(0xffffffffu, cmax0, 2));
        cmax1 = fmaxf(cmax1, __shfl_xor_sync(0xffffffffu, cmax1, 1));
        cmax1 = fmaxf(cmax1, __shfl_xor_sync(0xffffffffu, cmax1, 2));

        float nm0 = fmaxf(m0, cmax0), nm1 = fmaxf(m1, cmax1);
        float cr0 = ex2(m0 - nm0), cr1 = ex2(m1 - nm1);
        m0 = nm0; m1 = nm1;
        l0 *= cr0; l1 *= cr1;
        #pragma unroll
        for (int j = 0; j < 8; j++) {
            oacc[j][0] *= cr0; oacc[j][1] *= cr0;
            oacc[j][2] *= cr1; oacc[j][3] *= cr1;
        }
        #pragma unroll
        for (int j = 0; j < 8; j++) {
            s[j][0] = ex2(s[j][0] - nm0);
            s[j][1] = ex2(s[j][1] - nm0);
            s[j][2] = ex2(s[j][2] - nm1);
            s[j][3] = ex2(s[j][3] - nm1);
            l0 += s[j][0] + s[j][1];
            l1 += s[j][2] + s[j][3];
        }

        #pragma unroll
        for (int kt = 0; kt < 4; kt++) {
            unsigned pa0, pa1, pa2, pa3;
            {
                __nv_bfloat162 t;
                t = __floats2bfloat162_rn(s[2*kt][0],   s[2*kt][1]);   pa0 = *(unsigned*)&t;
                t = __floats2bfloat162_rn(s[2*kt][2],   s[2*kt][3]);   pa1 = *(unsigned*)&t;
                t = __floats2bfloat162_rn(s[2*kt+1][0], s[2*kt+1][1]); pa2 = *(unsigned*)&t;
                t = __floats2bfloat162_rn(s[2*kt+1][2], s[2*kt+1][3]); pa3 = *(unsigned*)&t;
            }
            #pragma unroll
            for (int dp = 0; dp < 4; dp++) {
                uint4 Vf = ldm_x4t(sv + voff0 + kt * 16 * APITCHB + dp * 32);
                mma16816(oacc[dp * 2 + 0], pa0, pa1, pa2, pa3, Vf.x, Vf.y);
                mma16816(oacc[dp * 2 + 1], pa0, pa1, pa2, pa3, Vf.z, Vf.w);
            }
        }
        __syncthreads();
    }

    l0 += __shfl_xor_sync(0xffffffffu, l0, 1);
    l0 += __shfl_xor_sync(0xffffffffu, l0, 2);
    l1 += __shfl_xor_sync(0xffffffffu, l1, 1);
    l1 += __shfl_xor_sync(0xffffffffu, l1, 2);
    float inv0 = 1.f / l0, inv1 = 1.f / l1;

    #pragma unroll
    for (int j = 0; j < 8; j++) {
        int n0 = h * HD + j * 8 + 2 * tg;
        __nv_bfloat162 p0 = __floats2bfloat162_rn(oacc[j][0] * inv0, oacc[j][1] * inv0);
        __nv_bfloat162 p1 = __floats2bfloat162_rn(oacc[j][2] * inv1, oacc[j][3] * inv1);
        *(__nv_bfloat162*)(yb + (size_t)(b * TT + t0) * (NH * HD) + n0) = p0;
        *(__nv_bfloat162*)(yb + (size_t)(b * TT + t1) * (NH * HD) + n0) = p1;
    }
}

// ---------------- launch ----------------
extern "C" void kernel_launch(void* const* d_in, const int* in_sizes, int n_in,
                              void* d_out, int out_size)
{
    const float* x            = (const float*)d_in[0];
    const float* wq           = (const float*)d_in[1];
    const float* wk           = (const float*)d_in[2];
    const float* wv           = (const float*)d_in[3];
    const float* wo           = (const float*)d_in[4];
    const float* w1           = (const float*)d_in[5];
    const float* w2           = (const float*)d_in[6];
    const float* w3           = (const float*)d_in[7];
    const float* q_norm_w     = (const float*)d_in[8];
    const float* k_norm_w     = (const float*)d_in[9];
    const float* attn_norm_w  = (const float*)d_in[10];
    const float* ffn_norm_w   = (const float*)d_in[11];
    const float* attn_scale   = (const float*)d_in[12];
    const float* ffn_scale    = (const float*)d_in[13];
    float* out = (float*)d_out;

    __nv_bfloat16 *xnb, *qkv, *qbp, *kbp, *vbp, *yb, *hnb, *a1, *gb;
    __nv_bfloat16 *wqkv, *wob, *w1b, *w3b, *w2b;
    float *h;
    cudaGetSymbolAddress((void**)&xnb,  g_xnb);
    cudaGetSymbolAddress((void**)&qkv,  g_qkv);
    cudaGetSymbolAddress((void**)&qbp,  g_qb);
    cudaGetSymbolAddress((void**)&kbp,  g_kb);
    cudaGetSymbolAddress((void**)&vbp,  g_vb);
    cudaGetSymbolAddress((void**)&yb,   g_yb);
    cudaGetSymbolAddress((void**)&h,    g_h);
    cudaGetSymbolAddress((void**)&hnb,  g_hnb);
    cudaGetSymbolAddress((void**)&a1,   g_a1);
    cudaGetSymbolAddress((void**)&gb,   g_gb);
    cudaGetSymbolAddress((void**)&wqkv, g_wqkv);
    cudaGetSymbolAddress((void**)&wob,  g_wob);
    cudaGetSymbolAddress((void**)&w1b,  g_w1b);
    cudaGetSymbolAddress((void**)&w3b,  g_w3b);
    cudaGetSymbolAddress((void**)&w2b,  g_w2b);

    const int M = MROWS;
    const int smem_bytes = GSMEM;
    cudaFuncSetAttribute(gemm_kernel<0>, cudaFuncAttributeMaxDynamicSharedMemorySize, smem_bytes);
    cudaFuncSetAttribute(gemm_kernel<1>, cudaFuncAttributeMaxDynamicSharedMemorySize, smem_bytes);
    cudaFuncSetAttribute(gemm_kernel<2>, cudaFuncAttributeMaxDynamicSharedMemorySize, smem_bytes);
    cudaFuncSetAttribute(gemm_kernel<3>, cudaFuncAttributeMaxDynamicSharedMemorySize, smem_bytes);

    // 0) all weight conversions in one launch
    wconv_kernel<<<(R6 + 255) / 256, 256>>>(wq, wk, wv, wo, w1, w3, w2,
                                            wqkv, wob, w1b, w3b, w2b);

    // 1) attn pre-norm
    rmsnorm_kernel<<<M, 256>>>(x, attn_norm_w, xnb, 1e-5f);

    // 2) fused QKV projection (bf16 out)
    gemm_kernel<3><<<dim3(QKVN/128, M/128), 256, smem_bytes>>>(
        xnb, wqkv, qkv, M, QKVN, DIM, nullptr, nullptr, nullptr);

    // 3) fused pack q/k/v (one launch)
    const float QSCALE = 0.125f * 1.4426950408889634f;
    packall_kernel<<<(NQVEC + 2 * NKVEC) / 8, 256>>>(
        qkv, q_norm_w, k_norm_w, qbp, kbp, vbp, QSCALE);

    // 4) MMA flash attention
    fattn_kernel<<<dim3(TT / 128, BB * NH), 256>>>(qbp, kbp, vbp, yb);

    // 5) output projection + residual + layer scale -> h
    gemm_kernel<1><<<dim3(DIM/128, M/128), 256, smem_bytes>>>(
        yb, wob, h, M, DIM, NH*HD, x, attn_scale, nullptr);

    // 6) ffn pre-norm
    rmsnorm_kernel<<<M, 256>>>(h, ffn_norm_w, hnb, 1e-5f);

    // 7) SwiGLU FFN
    gemm_kernel<3><<<dim3(HID/128, M/128), 256, smem_bytes>>>(
        hnb, w1b, a1, M, HID, DIM, nullptr, nullptr, nullptr);
    gemm_kernel<2><<<dim3(HID/128, M/128), 256, smem_bytes>>>(
        hnb, w3b, gb, M, HID, DIM, nullptr, nullptr, a1);
    gemm_kernel<1><<<dim3(DIM/128, M/128), 256, smem_bytes>>>(
        gb, w2b, out, M, DIM, HID, h, ffn_scale, nullptr);
}

// round 16
// speedup vs baseline: 1.2469x; 1.2469x over previous
#include <cuda_runtime.h>
#include <cuda_bf16.h>
#include <math.h>

#define BB 2
#define TT 2048
#define DIM 1024
#define HID 4096
#define NH 16
#define KVH 4
#define HD 64
#define WIN 512
#define MROWS (BB*TT)       // 4096
#define QKVN 1536

// ---------------- scratch ----------------
__device__ __nv_bfloat16 g_xnb[MROWS * DIM];
__device__ __nv_bfloat16 g_qkv[MROWS * QKVN];
__device__ __nv_bfloat16 g_qb [BB * NH  * TT * HD];
__device__ __nv_bfloat16 g_kb [BB * KVH * TT * HD];
__device__ __nv_bfloat16 g_vb [BB * KVH * TT * HD];
__device__ __nv_bfloat16 g_yb [MROWS * NH * HD];
__device__ float         g_h  [MROWS * DIM];
__device__ __nv_bfloat16 g_hnb[MROWS * DIM];
__device__ __nv_bfloat16 g_a1 [MROWS * HID];
__device__ __nv_bfloat16 g_gb [MROWS * HID];
__device__ __nv_bfloat16 g_wqkv[QKVN * DIM];
__device__ __nv_bfloat16 g_wob [DIM * NH * HD];
__device__ __nv_bfloat16 g_w1b [HID * DIM];
__device__ __nv_bfloat16 g_w3b [HID * DIM];
__device__ __nv_bfloat16 g_w2b [DIM * HID];

// ---------------- helpers ----------------
__device__ __forceinline__ void cp16(unsigned saddr, const void* g) {
    asm volatile("cp.async.cg.shared.global [%0], [%1], 16;\n" :: "r"(saddr), "l"(g));
}
__device__ __forceinline__ uint4 ldm_x4(unsigned addr) {
    uint4 r;
    asm volatile("ldmatrix.sync.aligned.m8n8.x4.shared.b16 {%0,%1,%2,%3}, [%4];\n"
                 : "=r"(r.x), "=r"(r.y), "=r"(r.z), "=r"(r.w) : "r"(addr));
    return r;
}
__device__ __forceinline__ uint4 ldm_x4t(unsigned addr) {
    uint4 r;
    asm volatile("ldmatrix.sync.aligned.m8n8.x4.trans.shared.b16 {%0,%1,%2,%3}, [%4];\n"
                 : "=r"(r.x), "=r"(r.y), "=r"(r.z), "=r"(r.w) : "r"(addr));
    return r;
}
__device__ __forceinline__ float ex2(float x) {
    float r; asm("ex2.approx.f32 %0, %1;" : "=f"(r) : "f"(x)); return r;
}
__device__ __forceinline__ void mma16816(
    float* c, unsigned a0, unsigned a1, unsigned a2, unsigned a3,
    unsigned b0, unsigned b1)
{
    asm volatile(
        "mma.sync.aligned.m16n8k16.row.col.f32.bf16.bf16.f32 "
        "{%0,%1,%2,%3}, {%4,%5,%6,%7}, {%8,%9}, {%0,%1,%2,%3};"
        : "+f"(c[0]), "+f"(c[1]), "+f"(c[2]), "+f"(c[3])
        : "r"(a0), "r"(a1), "r"(a2), "r"(a3), "r"(b0), "r"(b1));
}

// ---------------- fused weight conversion ----------------
#define R0 ((NH*HD*DIM)/4)
#define R1 (R0 + (KVH*HD*DIM)/4)
#define R2 (R1 + (KVH*HD*DIM)/4)
#define R3 (R2 + (DIM*NH*HD)/4)
#define R4 (R3 + (HID*DIM)/4)
#define R5 (R4 + (HID*DIM)/4)
#define R6 (R5 + (DIM*HID)/4)

__global__ __launch_bounds__(256) void wconv_kernel(
    const float* __restrict__ wq, const float* __restrict__ wk,
    const float* __restrict__ wv, const float* __restrict__ wo,
    const float* __restrict__ w1, const float* __restrict__ w3,
    const float* __restrict__ w2,
    __nv_bfloat16* __restrict__ wqkv, __nv_bfloat16* __restrict__ wob,
    __nv_bfloat16* __restrict__ w1b, __nv_bfloat16* __restrict__ w3b,
    __nv_bfloat16* __restrict__ w2b)
{
    int i = blockIdx.x * 256 + threadIdx.x;
    if (i >= R6) return;
    const float* s; __nv_bfloat16* d; int off;
    if (i < R0)      { s = wq; d = wqkv;                       off = i; }
    else if (i < R1) { s = wk; d = wqkv + NH*HD*DIM;           off = i - R0; }
    else if (i < R2) { s = wv; d = wqkv + (NH+KVH)*HD*DIM;     off = i - R1; }
    else if (i < R3) { s = wo; d = wob;                        off = i - R2; }
    else if (i < R4) { s = w1; d = w1b;                        off = i - R3; }
    else if (i < R5) { s = w3; d = w3b;                        off = i - R4; }
    else             { s = w2; d = w2b;                        off = i - R5; }
    float4 v = ((const float4*)s)[off];
    __nv_bfloat162 lo = __floats2bfloat162_rn(v.x, v.y);
    __nv_bfloat162 hi = __floats2bfloat162_rn(v.z, v.w);
    uint2 r; r.x = *(unsigned*)&lo; r.y = *(unsigned*)&hi;
    ((uint2*)d)[off] = r;
}

// ---------------- RMSNorm over DIM=1024, bf16 out ----------------
__global__ __launch_bounds__(256) void rmsnorm_kernel(
    const float* __restrict__ x, const float* __restrict__ w,
    __nv_bfloat16* __restrict__ out, float eps)
{
    int row = blockIdx.x;
    int tid = threadIdx.x;
    const float4* xr = (const float4*)(x + (size_t)row * DIM);
    float4 xv = xr[tid];
    float acc = xv.x*xv.x + xv.y*xv.y + xv.z*xv.z + xv.w*xv.w;

    __shared__ float red[8];
    #pragma unroll
    for (int o = 16; o > 0; o >>= 1) acc += __shfl_xor_sync(0xffffffffu, acc, o);
    if ((tid & 31) == 0) red[tid >> 5] = acc;
    __syncthreads();
    if (tid < 8) {
        float a = red[tid];
        #pragma unroll
        for (int o = 4; o > 0; o >>= 1) a += __shfl_xor_sync(0xffu, a, o);
        if (tid == 0) red[0] = a;
    }
    __syncthreads();
    float r = rsqrtf(red[0] * (1.0f / DIM) + eps);

    float4 wv = ((const float4*)w)[tid];
    __nv_bfloat162 lo = __floats2bfloat162_rn(xv.x * r * wv.x, xv.y * r * wv.y);
    __nv_bfloat162 hi = __floats2bfloat162_rn(xv.z * r * wv.z, xv.w * r * wv.w);
    uint2 ov; ov.x = *(unsigned*)&lo; ov.y = *(unsigned*)&hi;
    ((uint2*)(out + (size_t)row * DIM))[tid] = ov;
}

// ---------------- fused pack q/k/v ----------------
#define NQVEC (MROWS * NH)
#define NKVEC (MROWS * KVH)
__global__ __launch_bounds__(256) void packall_kernel(
    const __nv_bfloat16* __restrict__ qkv,
    const float* __restrict__ qw, const float* __restrict__ kw,
    __nv_bfloat16* __restrict__ qd, __nv_bfloat16* __restrict__ kd,
    __nv_bfloat16* __restrict__ vd, float qscale)
{
    int vec = blockIdx.x * 8 + (threadIdx.x >> 5);
    int lane = threadIdx.x & 31;

    int mode, idx;
    if (vec < NQVEC)               { mode = 0; idx = vec; }
    else if (vec < NQVEC + NKVEC)  { mode = 1; idx = vec - NQVEC; }
    else                           { mode = 2; idx = vec - NQVEC - NKVEC; }

    int nh = (mode == 0) ? NH : KVH;
    int colOff = (mode == 0) ? 0 : (mode == 1 ? NH * HD : (NH + KVH) * HD);
    int row = idx / nh, hh = idx % nh;
    int b = row / TT, t = row % TT;

    __nv_bfloat162 tv = ((const __nv_bfloat162*)(qkv + (size_t)row * QKVN + colOff + hh * HD))[lane];
    float vx = __bfloat162float(tv.x), vy = __bfloat162float(tv.y);

    float r = 1.0f, sc = 1.0f;
    float wx = 1.f, wy = 1.f;
    if (mode < 2) {
        float acc = vx * vx + vy * vy;
        #pragma unroll
        for (int o = 16; o > 0; o >>= 1) acc += __shfl_xor_sync(0xffffffffu, acc, o);
        r = rsqrtf(acc * (1.0f / HD) + 1e-6f);
        const float* wp = (mode == 0) ? qw : kw;
        float2 wv = ((const float2*)wp)[lane];
        wx = wv.x; wy = wv.y;
        if (mode == 0) sc = qscale;
    }
    __nv_bfloat16* dst = (mode == 0) ? qd : (mode == 1 ? kd : vd);
    __nv_bfloat162 ob = __floats2bfloat162_rn(vx * r * wx * sc, vy * r * wy * sc);
    *(__nv_bfloat162*)(dst + (((size_t)(b * nh + hh) * TT + t) * HD) + lane * 2) = ob;
}

// ---------------- bf16 GEMM: 128x128x64 block, 8 warps (2Mx4N), 64x32 warp tile ----
// 4-stage cp.async ring (R10 structure, one stage deeper) + grouped rasterization
#define STAGES 4
#define KT 64
#define PITCHB 144
#define OPBYTES (128 * PITCHB)
#define STAGE_BYTES (2 * OPBYTES)
#define GSMEM (STAGES * STAGE_BYTES)   // 147456

// EPI 0: fp32 store; 1: fp32 res+scale; 2: bf16 silu(other_bf16)*acc; 3: bf16 store
template <int EPI>
__global__ __launch_bounds__(256) void gemm_kernel(
    const __nv_bfloat16* __restrict__ A, const __nv_bfloat16* __restrict__ W,
    void* __restrict__ Cv, int M, int N, int K,
    const float* __restrict__ res, const float* __restrict__ scale,
    const __nv_bfloat16* __restrict__ other)
{
    extern __shared__ char smem[];

    // grouped rasterization (GROUP_M = 8) for L2 reuse
    int num_pid_m = gridDim.y, num_pid_n = gridDim.x;
    int pid = blockIdx.y * num_pid_n + blockIdx.x;
    int num_in_group = 8 * num_pid_n;
    int group_id = pid / num_in_group;
    int first_m = group_id * 8;
    int gsz = min(num_pid_m - first_m, 8);
    int pid_m = first_m + (pid % gsz);
    int pid_n = (pid % num_in_group) / gsz;

    const int bm = pid_m * 128;
    const int bn = pid_n * 128;
    const int tid = threadIdx.x;
    const int warpId = tid >> 5, lane = tid & 31;
    const int gid = lane >> 2, tg = lane & 3;
    const int warpM = warpId & 1, warpN = warpId >> 1;
    const int r8 = lane & 7;

    const unsigned sbase = (unsigned)__cvta_generic_to_shared(smem);
    const int ktiles = K >> 6;

    float acc[4][4][4];
    #pragma unroll
    for (int mi = 0; mi < 4; mi++)
        #pragma unroll
        for (int ni = 0; ni < 4; ni++)
            #pragma unroll
            for (int c = 0; c < 4; c++) acc[mi][ni][c] = 0.f;

    auto fetch = [&](int s, int kt) {
        if (kt < ktiles) {
            unsigned sa = sbase + s * STAGE_BYTES;
            unsigned sb = sa + OPBYTES;
            #pragma unroll
            for (int i = 0; i < 4; i++) {
                int chunk = tid + i * 256;
                int row = chunk >> 3, c = chunk & 7;
                size_t go = (size_t)row * K + (size_t)kt * KT + c * 8;
                cp16(sa + row * PITCHB + c * 16, A + (size_t)bm * K + go);
                cp16(sb + row * PITCHB + c * 16, W + (size_t)bn * K + go);
            }
        }
    };

    unsigned aoff[4], boff[2];
    #pragma unroll
    for (int mi = 0; mi < 4; mi++)
        aoff[mi] = (warpM * 64 + mi * 16 + ((lane >> 3) & 1) * 8 + r8) * PITCHB + (lane >> 4) * 16;
    #pragma unroll
    for (int np = 0; np < 2; np++)
        boff[np] = (warpN * 32 + np * 16 + (lane >> 4) * 8 + r8) * PITCHB + ((lane >> 3) & 1) * 16;

    fetch(0, 0);
    asm volatile("cp.async.commit_group;\n" ::: "memory");
    fetch(1, 1);
    asm volatile("cp.async.commit_group;\n" ::: "memory");
    fetch(2, 2);
    asm volatile("cp.async.commit_group;\n" ::: "memory");

    for (int kt = 0; kt < ktiles; kt++) {
        asm volatile("cp.async.wait_group 2;\n" ::: "memory");
        __syncthreads();

        fetch((kt + 3) & (STAGES - 1), kt + 3);
        asm volatile("cp.async.commit_group;\n" ::: "memory");

        const unsigned sa = sbase + (kt & (STAGES - 1)) * STAGE_BYTES;
        const unsigned sb = sa + OPBYTES;

        #pragma unroll
        for (int ks = 0; ks < 4; ks++) {
            uint4 Af[4], Bf[2];
            #pragma unroll
            for (int mi = 0; mi < 4; mi++) Af[mi] = ldm_x4(sa + aoff[mi] + ks * 32);
            #pragma unroll
            for (int np = 0; np < 2; np++) Bf[np] = ldm_x4(sb + boff[np] + ks * 32);
            #pragma unroll
            for (int mi = 0; mi < 4; mi++) {
                mma16816(acc[mi][0], Af[mi].x, Af[mi].y, Af[mi].z, Af[mi].w, Bf[0].x, Bf[0].y);
                mma16816(acc[mi][1], Af[mi].x, Af[mi].y, Af[mi].z, Af[mi].w, Bf[0].z, Bf[0].w);
                mma16816(acc[mi][2], Af[mi].x, Af[mi].y, Af[mi].z, Af[mi].w, Bf[1].x, Bf[1].y);
                mma16816(acc[mi][3], Af[mi].x, Af[mi].y, Af[mi].z, Af[mi].w, Bf[1].z, Bf[1].w);
            }
        }
    }

    #pragma unroll
    for (int mi = 0; mi < 4; mi++) {
        #pragma unroll
        for (int ni = 0; ni < 4; ni++) {
            int m0 = bm + warpM * 64 + mi * 16 + gid;
            int n0 = bn + warpN * 32 + ni * 8 + tg * 2;
            #pragma unroll
            for (int half = 0; half < 2; half++) {
                int m = m0 + half * 8;
                size_t base = (size_t)m * N + n0;
                float v0 = acc[mi][ni][half * 2 + 0];
                float v1 = acc[mi][ni][half * 2 + 1];
                if (EPI == 0) {
                    float2 ov; ov.x = v0; ov.y = v1;
                    *(float2*)((float*)Cv + base) = ov;
                } else if (EPI == 1) {
                    v0 = res[base + 0] + v0 * scale[n0 + 0];
                    v1 = res[base + 1] + v1 * scale[n0 + 1];
                    float2 ov; ov.x = v0; ov.y = v1;
                    *(float2*)((float*)Cv + base) = ov;
                } else if (EPI == 2) {
                    __nv_bfloat162 ab = *(const __nv_bfloat162*)(other + base);
                    float a0 = __bfloat162float(ab.x);
                    float a1 = __bfloat162float(ab.y);
                    v0 = (a0 / (1.f + __expf(-a0))) * v0;
                    v1 = (a1 / (1.f + __expf(-a1))) * v1;
                    __nv_bfloat162 p = __floats2bfloat162_rn(v0, v1);
                    *(__nv_bfloat162*)((__nv_bfloat16*)Cv + base) = p;
                } else {
                    __nv_bfloat162 p = __floats2bfloat162_rn(v0, v1);
                    *(__nv_bfloat162*)((__nv_bfloat16*)Cv + base) = p;
                }
            }
        }
    }
}

// ---------------- MMA flash attention, sliding window, GQA ----------------
#define ACK 64
#define APITCHB 144
#define AOP (ACK * APITCHB)
#define ASTAGE (2 * AOP)

__global__ __launch_bounds__(256) void fattn_kernel(
    const __nv_bfloat16* __restrict__ qb, const __nv_bfloat16* __restrict__ kb,
    const __nv_bfloat16* __restrict__ vb, __nv_bfloat16* __restrict__ yb)
{
    __shared__ char asmem[2 * ASTAGE];
    const int qt = blockIdx.x, bh = blockIdx.y;
    const int b = bh / NH, h = bh % NH;
    const int kvh = h / (NH / KVH);
    const int tid = threadIdx.x;
    const int w = tid >> 5, lane = tid & 31;
    const int gid = lane >> 2, tg = lane & 3;
    const int r8 = lane & 7;
    const int q0 = qt * 128;
    const int t0 = q0 + w * 16 + gid;
    const int t1 = t0 + 8;

    const unsigned sbase = (unsigned)__cvta_generic_to_shared(asmem);

    const __nv_bfloat16* qbase = qb + (size_t)(b * NH + h) * TT * HD;
    unsigned qa[4][4];
    #pragma unroll
    for (int kt = 0; kt < 4; kt++) {
        qa[kt][0] = *(const unsigned*)(qbase + (size_t)t0 * HD + kt * 16 + 2 * tg);
        qa[kt][1] = *(const unsigned*)(qbase + (size_t)t1 * HD + kt * 16 + 2 * tg);
        qa[kt][2] = *(const unsigned*)(qbase + (size_t)t0 * HD + kt * 16 + 8 + 2 * tg);
        qa[kt][3] = *(const unsigned*)(qbase + (size_t)t1 * HD + kt * 16 + 8 + 2 * tg);
    }

    float oacc[8][4];
    #pragma unroll
    for (int j = 0; j < 8; j++)
        #pragma unroll
        for (int c = 0; c < 4; c++) oacc[j][c] = 0.f;
    float m0 = -1e30f, m1 = -1e30f, l0 = 0.f, l1 = 0.f;

    const int kstart = max(0, q0 - WIN + 1) & ~(ACK - 1);
    const int nch = (q0 + 128 - kstart) / ACK;

    const __nv_bfloat16* kbase = kb + (size_t)(b * KVH + kvh) * TT * HD;
    const __nv_bfloat16* vbase = vb + (size_t)(b * KVH + kvh) * TT * HD;

    auto fetch = [&](int s, int kc) {
        unsigned sk = sbase + s * ASTAGE;
        unsigned sv = sk + AOP;
        #pragma unroll
        for (int i = 0; i < 2; i++) {
            int chunk = tid + i * 256;
            int row = chunk >> 3, c = chunk & 7;
            cp16(sk + row * APITCHB + c * 16, kbase + (size_t)(kc + row) * HD + c * 8);
            cp16(sv + row * APITCHB + c * 16, vbase + (size_t)(kc + row) * HD + c * 8);
        }
    };

    unsigned koff[4], voff0;
    #pragma unroll
    for (int np = 0; np < 4; np++)
        koff[np] = (np * 16 + (lane >> 4) * 8 + r8) * APITCHB + ((lane >> 3) & 1) * 16;
    voff0 = (((lane >> 3) & 1) * 8 + r8) * APITCHB + (lane >> 4) * 16;

    fetch(0, kstart);
    asm volatile("cp.async.commit_group;\n" ::: "memory");

    for (int ci = 0; ci < nch; ci++) {
        int kc = kstart + ci * ACK;
        bool more = (ci + 1 < nch);
        if (more) {
            fetch((ci + 1) & 1, kc + ACK);
            asm volatile("cp.async.commit_group;\n" ::: "memory");
            asm volatile("cp.async.wait_group 1;\n" ::: "memory");
        } else {
            asm volatile("cp.async.wait_group 0;\n" ::: "memory");
        }
        __syncthreads();

        const unsigned sk = sbase + (ci & 1) * ASTAGE;
        const unsigned sv = sk + AOP;

        float s[8][4];
        #pragma unroll
        for (int j = 0; j < 8; j++)
            #pragma unroll
            for (int c = 0; c < 4; c++) s[j][c] = 0.f;
        #pragma unroll
        for (int ks = 0; ks < 4; ks++) {
            #pragma unroll
            for (int np = 0; np < 4; np++) {
                uint4 Bf = ldm_x4(sk + koff[np] + ks * 32);
                mma16816(s[np * 2 + 0], qa[ks][0], qa[ks][1], qa[ks][2], qa[ks][3], Bf.x, Bf.y);
                mma16816(s[np * 2 + 1], qa[ks][0], qa[ks][1], qa[ks][2], qa[ks][3], Bf.z, Bf.w);
            }
        }

        float cmax0 = -INFINITY, cmax1 = -INFINITY;
        #pragma unroll
        for (int j = 0; j < 8; j++) {
            int col = kc + j * 8 + 2 * tg;
            #pragma unroll
            for (int cc = 0; cc < 2; cc++) {
                int c0 = col + cc;
                if (!(c0 <= t0 && (t0 - c0) < WIN)) s[j][cc] = -INFINITY;
                if (!(c0 <= t1 && (t1 - c0) < WIN)) s[j][2 + cc] = -INFINITY;
            }
            cmax0 = fmaxf(cmax0, fmaxf(s[j][0], s[j][1]));
            cmax1 = fmaxf(cmax1, fmaxf(s[j][2], s[j][3]));
        }
        cmax0 = fmaxf(cmax0, __shfl_xor_sync(0xffffffffu, cmax0, 1));
        cmax0 = fmaxf(cmax0, __shfl_xor_sync(0xffffffffu, cmax0, 2));
        cmax1 = fmaxf(cmax1, __shfl_xor_sync(0xffffffffu, cmax1, 1));
        cmax1 = fmaxf(cmax1, __shfl_xor_sync(0xffffffffu, cmax1, 2));

        float nm0 = fmaxf(m0, cmax0), nm1 = fmaxf(m1, cmax1);
        float cr0 = ex2(m0 - nm0), cr1 = ex2(m1 - nm1);
        m0 = nm0; m1 = nm1;
        l0 *= cr0; l1 *= cr1;
        #pragma unroll
        for (int j = 0; j < 8; j++) {
            oacc[j][0] *= cr0; oacc[j][1] *= cr0;
            oacc[j][2] *= cr1; oacc[j][3] *= cr1;
        }
        #pragma unroll
        for (int j = 0; j < 8; j++) {
            s[j][0] = ex2(s[j][0] - nm0);
            s[j][1] = ex2(s[j][1] - nm0);
            s[j][2] = ex2(s[j][2] - nm1);
            s[j][3] = ex2(s[j][3] - nm1);
            l0 += s[j][0] + s[j][1];
            l1 += s[j][2] + s[j][3];
        }

        #pragma unroll
        for (int kt = 0; kt < 4; kt++) {
            unsigned pa0, pa1, pa2, pa3;
            {
                __nv_bfloat162 t;
                t = __floats2bfloat162_rn(s[2*kt][0],   s[2*kt][1]);   pa0 = *(unsigned*)&t;
                t = __floats2bfloat162_rn(s[2*kt][2],   s[2*kt][3]);   pa1 = *(unsigned*)&t;
                t = __floats2bfloat162_rn(s[2*kt+1][0], s[2*kt+1][1]); pa2 = *(unsigned*)&t;
                t = __floats2bfloat162_rn(s[2*kt+1][2], s[2*kt+1][3]); pa3 = *(unsigned*)&t;
            }
            #pragma unroll
            for (int dp = 0; dp < 4; dp++) {
                uint4 Vf = ldm_x4t(sv + voff0 + kt * 16 * APITCHB + dp * 32);
                mma16816(oacc[dp * 2 + 0], pa0, pa1, pa2, pa3, Vf.x, Vf.y);
                mma16816(oacc[dp * 2 + 1], pa0, pa1, pa2, pa3, Vf.z, Vf.w);
            }
        }
        __syncthreads();
    }

    l0 += __shfl_xor_sync(0xffffffffu, l0, 1);
    l0 += __shfl_xor_sync(0xffffffffu, l0, 2);
    l1 += __shfl_xor_sync(0xffffffffu, l1, 1);
    l1 += __shfl_xor_sync(0xffffffffu, l1, 2);
    float inv0 = 1.f / l0, inv1 = 1.f / l1;

    #pragma unroll
    for (int j = 0; j < 8; j++) {
        int n0 = h * HD + j * 8 + 2 * tg;
        __nv_bfloat162 p0 = __floats2bfloat162_rn(oacc[j][0] * inv0, oacc[j][1] * inv0);
        __nv_bfloat162 p1 = __floats2bfloat162_rn(oacc[j][2] * inv1, oacc[j][3] * inv1);
        *(__nv_bfloat162*)(yb + (size_t)(b * TT + t0) * (NH * HD) + n0) = p0;
        *(__nv_bfloat162*)(yb + (size_t)(b * TT + t1) * (NH * HD) + n0) = p1;
    }
}

// ---------------- launch ----------------
extern "C" void kernel_launch(void* const* d_in, const int* in_sizes, int n_in,
                              void* d_out, int out_size)
{
    const float* x            = (const float*)d_in[0];
    const float* wq           = (const float*)d_in[1];
    const float* wk           = (const float*)d_in[2];
    const float* wv           = (const float*)d_in[3];
    const float* wo           = (const float*)d_in[4];
    const float* w1           = (const float*)d_in[5];
    const float* w2           = (const float*)d_in[6];
    const float* w3           = (const float*)d_in[7];
    const float* q_norm_w     = (const float*)d_in[8];
    const float* k_norm_w     = (const float*)d_in[9];
    const float* attn_norm_w  = (const float*)d_in[10];
    const float* ffn_norm_w   = (const float*)d_in[11];
    const float* attn_scale   = (const float*)d_in[12];
    const float* ffn_scale    = (const float*)d_in[13];
    float* out = (float*)d_out;

    __nv_bfloat16 *xnb, *qkv, *qbp, *kbp, *vbp, *yb, *hnb, *a1, *gb;
    __nv_bfloat16 *wqkv, *wob, *w1b, *w3b, *w2b;
    float *h;
    cudaGetSymbolAddress((void**)&xnb,  g_xnb);
    cudaGetSymbolAddress((void**)&qkv,  g_qkv);
    cudaGetSymbolAddress((void**)&qbp,  g_qb);
    cudaGetSymbolAddress((void**)&kbp,  g_kb);
    cudaGetSymbolAddress((void**)&vbp,  g_vb);
    cudaGetSymbolAddress((void**)&yb,   g_yb);
    cudaGetSymbolAddress((void**)&h,    g_h);
    cudaGetSymbolAddress((void**)&hnb,  g_hnb);
    cudaGetSymbolAddress((void**)&a1,   g_a1);
    cudaGetSymbolAddress((void**)&gb,   g_gb);
    cudaGetSymbolAddress((void**)&wqkv, g_wqkv);
    cudaGetSymbolAddress((void**)&wob,  g_wob);
    cudaGetSymbolAddress((void**)&w1b,  g_w1b);
    cudaGetSymbolAddress((void**)&w3b,  g_w3b);
    cudaGetSymbolAddress((void**)&w2b,  g_w2b);

    const int M = MROWS;
    const int smem_bytes = GSMEM;
    cudaFuncSetAttribute(gemm_kernel<0>, cudaFuncAttributeMaxDynamicSharedMemorySize, smem_bytes);
    cudaFuncSetAttribute(gemm_kernel<1>, cudaFuncAttributeMaxDynamicSharedMemorySize, smem_bytes);
    cudaFuncSetAttribute(gemm_kernel<2>, cudaFuncAttributeMaxDynamicSharedMemorySize, smem_bytes);
    cudaFuncSetAttribute(gemm_kernel<3>, cudaFuncAttributeMaxDynamicSharedMemorySize, smem_bytes);

    // 0) all weight conversions in one launch
    wconv_kernel<<<(R6 + 255) / 256, 256>>>(wq, wk, wv, wo, w1, w3, w2,
                                            wqkv, wob, w1b, w3b, w2b);

    // 1) attn pre-norm
    rmsnorm_kernel<<<M, 256>>>(x, attn_norm_w, xnb, 1e-5f);

    // 2) fused QKV projection (bf16 out)
    gemm_kernel<3><<<dim3(QKVN/128, M/128), 256, smem_bytes>>>(
        xnb, wqkv, qkv, M, QKVN, DIM, nullptr, nullptr, nullptr);

    // 3) fused pack q/k/v (one launch)
    const float QSCALE = 0.125f * 1.4426950408889634f;
    packall_kernel<<<(NQVEC + 2 * NKVEC) / 8, 256>>>(
        qkv, q_norm_w, k_norm_w, qbp, kbp, vbp, QSCALE);

    // 4) MMA flash attention
    fattn_kernel<<<dim3(TT / 128, BB * NH), 256>>>(qbp, kbp, vbp, yb);

    // 5) output projection + residual + layer scale -> h
    gemm_kernel<1><<<dim3(DIM/128, M/128), 256, smem_bytes>>>(
        yb, wob, h, M, DIM, NH*HD, x, attn_scale, nullptr);

    // 6) ffn pre-norm
    rmsnorm_kernel<<<M, 256>>>(h, ffn_norm_w, hnb, 1e-5f);

    // 7) SwiGLU FFN
    gemm_kernel<3><<<dim3(HID/128, M/128), 256, smem_bytes>>>(
        hnb, w1b, a1, M, HID, DIM, nullptr, nullptr, nullptr);
    gemm_kernel<2><<<dim3(HID/128, M/128), 256, smem_bytes>>>(
        hnb, w3b, gb, M, HID, DIM, nullptr, nullptr, a1);
    gemm_kernel<1><<<dim3(DIM/128, M/128), 256, smem_bytes>>>(
        gb, w2b, out, M, DIM, HID, h, ffn_scale, nullptr);
}

// round 17
// speedup vs baseline: 1.6139x; 1.2943x over previous
#include <cuda_runtime.h>
#include <cuda_bf16.h>
#include <math.h>

#define BB 2
#define TT 2048
#define DIM 1024
#define HID 4096
#define NH 16
#define KVH 4
#define HD 64
#define WIN 512
#define MROWS (BB*TT)       // 4096
#define QKVN 1536

// ---------------- scratch ----------------
__device__ __nv_bfloat16 g_xnb[MROWS * DIM];
__device__ __nv_bfloat16 g_qkv[MROWS * QKVN];
__device__ __nv_bfloat16 g_qb [BB * NH  * TT * HD];
__device__ __nv_bfloat16 g_kb [BB * KVH * TT * HD];
__device__ __nv_bfloat16 g_vb [BB * KVH * TT * HD];
__device__ __nv_bfloat16 g_yb [MROWS * NH * HD];
__device__ float         g_h  [MROWS * DIM];
__device__ __nv_bfloat16 g_hnb[MROWS * DIM];
__device__ __nv_bfloat16 g_gb [MROWS * HID];
__device__ __nv_bfloat16 g_wqkv[QKVN * DIM];
__device__ __nv_bfloat16 g_wob [DIM * NH * HD];
__device__ __nv_bfloat16 g_w13 [2 * HID * DIM];   // interleaved: row 2i = w1_i, 2i+1 = w3_i
__device__ __nv_bfloat16 g_w2b [DIM * HID];

// ---------------- helpers ----------------
__device__ __forceinline__ void cp16(unsigned saddr, const void* g) {
    asm volatile("cp.async.cg.shared.global [%0], [%1], 16;\n" :: "r"(saddr), "l"(g));
}
__device__ __forceinline__ uint4 ldm_x4(unsigned addr) {
    uint4 r;
    asm volatile("ldmatrix.sync.aligned.m8n8.x4.shared.b16 {%0,%1,%2,%3}, [%4];\n"
                 : "=r"(r.x), "=r"(r.y), "=r"(r.z), "=r"(r.w) : "r"(addr));
    return r;
}
__device__ __forceinline__ uint4 ldm_x4t(unsigned addr) {
    uint4 r;
    asm volatile("ldmatrix.sync.aligned.m8n8.x4.trans.shared.b16 {%0,%1,%2,%3}, [%4];\n"
                 : "=r"(r.x), "=r"(r.y), "=r"(r.z), "=r"(r.w) : "r"(addr));
    return r;
}
__device__ __forceinline__ float ex2(float x) {
    float r; asm("ex2.approx.f32 %0, %1;" : "=f"(r) : "f"(x)); return r;
}
__device__ __forceinline__ void mma16816(
    float* c, unsigned a0, unsigned a1, unsigned a2, unsigned a3,
    unsigned b0, unsigned b1)
{
    asm volatile(
        "mma.sync.aligned.m16n8k16.row.col.f32.bf16.bf16.f32 "
        "{%0,%1,%2,%3}, {%4,%5,%6,%7}, {%8,%9}, {%0,%1,%2,%3};"
        : "+f"(c[0]), "+f"(c[1]), "+f"(c[2]), "+f"(c[3])
        : "r"(a0), "r"(a1), "r"(a2), "r"(a3), "r"(b0), "r"(b1));
}

// ---------------- fused weight conversion (w1/w3 interleaved into w13) ----------------
#define R0 ((NH*HD*DIM)/4)
#define R1 (R0 + (KVH*HD*DIM)/4)
#define R2 (R1 + (KVH*HD*DIM)/4)
#define R3 (R2 + (DIM*NH*HD)/4)
#define R4 (R3 + (HID*DIM)/4)
#define R5 (R4 + (HID*DIM)/4)
#define R6 (R5 + (DIM*HID)/4)
#define DQ (DIM/4)   // 256 float4 per DIM row

__global__ __launch_bounds__(256) void wconv_kernel(
    const float* __restrict__ wq, const float* __restrict__ wk,
    const float* __restrict__ wv, const float* __restrict__ wo,
    const float* __restrict__ w1, const float* __restrict__ w3,
    const float* __restrict__ w2,
    __nv_bfloat16* __restrict__ wqkv, __nv_bfloat16* __restrict__ wob,
    __nv_bfloat16* __restrict__ w13, __nv_bfloat16* __restrict__ w2b)
{
    int i = blockIdx.x * 256 + threadIdx.x;
    if (i >= R6) return;
    const float* s; __nv_bfloat16* d; int off, doff;
    if (i < R0)      { s = wq; d = wqkv;                   off = i;      doff = off; }
    else if (i < R1) { s = wk; d = wqkv + NH*HD*DIM;       off = i - R0; doff = off; }
    else if (i < R2) { s = wv; d = wqkv + (NH+KVH)*HD*DIM; off = i - R1; doff = off; }
    else if (i < R3) { s = wo; d = wob;                    off = i - R2; doff = off; }
    else if (i < R4) { s = w1; d = w13;                    off = i - R3;
                       doff = (2 * (off / DQ)) * DQ + (off % DQ); }
    else if (i < R5) { s = w3; d = w13;                    off = i - R4;
                       doff = (2 * (off / DQ) + 1) * DQ + (off % DQ); }
    else             { s = w2; d = w2b;                    off = i - R5; doff = off; }
    float4 v = ((const float4*)s)[off];
    __nv_bfloat162 lo = __floats2bfloat162_rn(v.x, v.y);
    __nv_bfloat162 hi = __floats2bfloat162_rn(v.z, v.w);
    uint2 r; r.x = *(unsigned*)&lo; r.y = *(unsigned*)&hi;
    ((uint2*)d)[doff] = r;
}

// ---------------- RMSNorm over DIM=1024, bf16 out ----------------
__global__ __launch_bounds__(256) void rmsnorm_kernel(
    const float* __restrict__ x, const float* __restrict__ w,
    __nv_bfloat16* __restrict__ out, float eps)
{
    int row = blockIdx.x;
    int tid = threadIdx.x;
    const float4* xr = (const float4*)(x + (size_t)row * DIM);
    float4 xv = xr[tid];
    float acc = xv.x*xv.x + xv.y*xv.y + xv.z*xv.z + xv.w*xv.w;

    __shared__ float red[8];
    #pragma unroll
    for (int o = 16; o > 0; o >>= 1) acc += __shfl_xor_sync(0xffffffffu, acc, o);
    if ((tid & 31) == 0) red[tid >> 5] = acc;
    __syncthreads();
    if (tid < 8) {
        float a = red[tid];
        #pragma unroll
        for (int o = 4; o > 0; o >>= 1) a += __shfl_xor_sync(0xffu, a, o);
        if (tid == 0) red[0] = a;
    }
    __syncthreads();
    float r = rsqrtf(red[0] * (1.0f / DIM) + eps);

    float4 wv = ((const float4*)w)[tid];
    __nv_bfloat162 lo = __floats2bfloat162_rn(xv.x * r * wv.x, xv.y * r * wv.y);
    __nv_bfloat162 hi = __floats2bfloat162_rn(xv.z * r * wv.z, xv.w * r * wv.w);
    uint2 ov; ov.x = *(unsigned*)&lo; ov.y = *(unsigned*)&hi;
    ((uint2*)(out + (size_t)row * DIM))[tid] = ov;
}

// ---------------- fused pack q/k/v ----------------
#define NQVEC (MROWS * NH)
#define NKVEC (MROWS * KVH)
__global__ __launch_bounds__(256) void packall_kernel(
    const __nv_bfloat16* __restrict__ qkv,
    const float* __restrict__ qw, const float* __restrict__ kw,
    __nv_bfloat16* __restrict__ qd, __nv_bfloat16* __restrict__ kd,
    __nv_bfloat16* __restrict__ vd, float qscale)
{
    int vec = blockIdx.x * 8 + (threadIdx.x >> 5);
    int lane = threadIdx.x & 31;

    int mode, idx;
    if (vec < NQVEC)               { mode = 0; idx = vec; }
    else if (vec < NQVEC + NKVEC)  { mode = 1; idx = vec - NQVEC; }
    else                           { mode = 2; idx = vec - NQVEC - NKVEC; }

    int nh = (mode == 0) ? NH : KVH;
    int colOff = (mode == 0) ? 0 : (mode == 1 ? NH * HD : (NH + KVH) * HD);
    int row = idx / nh, hh = idx % nh;
    int b = row / TT, t = row % TT;

    __nv_bfloat162 tv = ((const __nv_bfloat162*)(qkv + (size_t)row * QKVN + colOff + hh * HD))[lane];
    float vx = __bfloat162float(tv.x), vy = __bfloat162float(tv.y);

    float r = 1.0f, sc = 1.0f;
    float wx = 1.f, wy = 1.f;
    if (mode < 2) {
        float acc = vx * vx + vy * vy;
        #pragma unroll
        for (int o = 16; o > 0; o >>= 1) acc += __shfl_xor_sync(0xffffffffu, acc, o);
        r = rsqrtf(acc * (1.0f / HD) + 1e-6f);
        const float* wp = (mode == 0) ? qw : kw;
        float2 wv = ((const float2*)wp)[lane];
        wx = wv.x; wy = wv.y;
        if (mode == 0) sc = qscale;
    }
    __nv_bfloat16* dst = (mode == 0) ? qd : (mode == 1 ? kd : vd);
    __nv_bfloat162 ob = __floats2bfloat162_rn(vx * r * wx * sc, vy * r * wy * sc);
    *(__nv_bfloat162*)(dst + (((size_t)(b * nh + hh) * TT + t) * HD) + lane * 2) = ob;
}

// ---------------- bf16 GEMM: 128x128x64 block, 8 warps (2Mx4N), 64x32 warp tile ----
// R10 structure: 3-stage cp.async ring, single sync per k-tile
#define STAGES 3
#define KT 64
#define PITCHB 144
#define OPBYTES (128 * PITCHB)
#define STAGE_BYTES (2 * OPBYTES)
#define GSMEM (STAGES * STAGE_BYTES)

// EPI 0: fp32 store; 1: fp32 res+scale; 2: (unused); 3: bf16 store;
// EPI 4: fused SwiGLU gate — W is interleaved [w1;w3], writes bf16 silu(even)*odd at N/2 cols
template <int EPI>
__global__ __launch_bounds__(256) void gemm_kernel(
    const __nv_bfloat16* __restrict__ A, const __nv_bfloat16* __restrict__ W,
    void* __restrict__ Cv, int M, int N, int K,
    const float* __restrict__ res, const float* __restrict__ scale)
{
    extern __shared__ char smem[];
    const int bm = blockIdx.y * 128;
    const int bn = blockIdx.x * 128;
    const int tid = threadIdx.x;
    const int warpId = tid >> 5, lane = tid & 31;
    const int gid = lane >> 2, tg = lane & 3;
    const int warpM = warpId & 1, warpN = warpId >> 1;
    const int r8 = lane & 7;

    const unsigned sbase = (unsigned)__cvta_generic_to_shared(smem);
    const int ktiles = K >> 6;

    float acc[4][4][4];
    #pragma unroll
    for (int mi = 0; mi < 4; mi++)
        #pragma unroll
        for (int ni = 0; ni < 4; ni++)
            #pragma unroll
            for (int c = 0; c < 4; c++) acc[mi][ni][c] = 0.f;

    auto fetch = [&](int s, int kt) {
        if (kt < ktiles) {
            unsigned sa = sbase + s * STAGE_BYTES;
            unsigned sb = sa + OPBYTES;
            #pragma unroll
            for (int i = 0; i < 4; i++) {
                int chunk = tid + i * 256;
                int row = chunk >> 3, c = chunk & 7;
                size_t go = (size_t)row * K + (size_t)kt * KT + c * 8;
                cp16(sa + row * PITCHB + c * 16, A + (size_t)bm * K + go);
                cp16(sb + row * PITCHB + c * 16, W + (size_t)bn * K + go);
            }
        }
    };

    unsigned aoff[4], boff[2];
    #pragma unroll
    for (int mi = 0; mi < 4; mi++)
        aoff[mi] = (warpM * 64 + mi * 16 + ((lane >> 3) & 1) * 8 + r8) * PITCHB + (lane >> 4) * 16;
    #pragma unroll
    for (int np = 0; np < 2; np++)
        boff[np] = (warpN * 32 + np * 16 + (lane >> 4) * 8 + r8) * PITCHB + ((lane >> 3) & 1) * 16;

    fetch(0, 0);
    asm volatile("cp.async.commit_group;\n" ::: "memory");
    fetch(1, 1);
    asm volatile("cp.async.commit_group;\n" ::: "memory");

    for (int kt = 0; kt < ktiles; kt++) {
        asm volatile("cp.async.wait_group 1;\n" ::: "memory");
        __syncthreads();

        fetch((kt + 2) % STAGES, kt + 2);
        asm volatile("cp.async.commit_group;\n" ::: "memory");

        const unsigned sa = sbase + (kt % STAGES) * STAGE_BYTES;
        const unsigned sb = sa + OPBYTES;

        #pragma unroll
        for (int ks = 0; ks < 4; ks++) {
            uint4 Af[4], Bf[2];
            #pragma unroll
            for (int mi = 0; mi < 4; mi++) Af[mi] = ldm_x4(sa + aoff[mi] + ks * 32);
            #pragma unroll
            for (int np = 0; np < 2; np++) Bf[np] = ldm_x4(sb + boff[np] + ks * 32);
            #pragma unroll
            for (int mi = 0; mi < 4; mi++) {
                mma16816(acc[mi][0], Af[mi].x, Af[mi].y, Af[mi].z, Af[mi].w, Bf[0].x, Bf[0].y);
                mma16816(acc[mi][1], Af[mi].x, Af[mi].y, Af[mi].z, Af[mi].w, Bf[0].z, Bf[0].w);
                mma16816(acc[mi][2], Af[mi].x, Af[mi].y, Af[mi].z, Af[mi].w, Bf[1].x, Bf[1].y);
                mma16816(acc[mi][3], Af[mi].x, Af[mi].y, Af[mi].z, Af[mi].w, Bf[1].z, Bf[1].w);
            }
        }
    }

    #pragma unroll
    for (int mi = 0; mi < 4; mi++) {
        #pragma unroll
        for (int ni = 0; ni < 4; ni++) {
            int m0 = bm + warpM * 64 + mi * 16 + gid;
            int n0 = bn + warpN * 32 + ni * 8 + tg * 2;
            #pragma unroll
            for (int half = 0; half < 2; half++) {
                int m = m0 + half * 8;
                float v0 = acc[mi][ni][half * 2 + 0];
                float v1 = acc[mi][ni][half * 2 + 1];
                if (EPI == 4) {
                    // interleaved gate: col n0 = w1 row (n0/2), col n0+1 = w3 row (n0/2)
                    float g = (v0 / (1.f + __expf(-v0))) * v1;
                    size_t ob = (size_t)m * (N >> 1) + (n0 >> 1);
                    ((__nv_bfloat16*)Cv)[ob] = __float2bfloat16(g);
                } else {
                    size_t base = (size_t)m * N + n0;
                    if (EPI == 0) {
                        float2 ov; ov.x = v0; ov.y = v1;
                        *(float2*)((float*)Cv + base) = ov;
                    } else if (EPI == 1) {
                        v0 = res[base + 0] + v0 * scale[n0 + 0];
                        v1 = res[base + 1] + v1 * scale[n0 + 1];
                        float2 ov; ov.x = v0; ov.y = v1;
                        *(float2*)((float*)Cv + base) = ov;
                    } else {
                        __nv_bfloat162 p = __floats2bfloat162_rn(v0, v1);
                        *(__nv_bfloat162*)((__nv_bfloat16*)Cv + base) = p;
                    }
                }
            }
        }
    }
}

// ---------------- MMA flash attention, sliding window, GQA ----------------
#define ACK 64
#define APITCHB 144
#define AOP (ACK * APITCHB)
#define ASTAGE (2 * AOP)

__global__ __launch_bounds__(256) void fattn_kernel(
    const __nv_bfloat16* __restrict__ qb, const __nv_bfloat16* __restrict__ kb,
    const __nv_bfloat16* __restrict__ vb, __nv_bfloat16* __restrict__ yb)
{
    __shared__ char asmem[2 * ASTAGE];
    const int qt = blockIdx.x, bh = blockIdx.y;
    const int b = bh / NH, h = bh % NH;
    const int kvh = h / (NH / KVH);
    const int tid = threadIdx.x;
    const int w = tid >> 5, lane = tid & 31;
    const int gid = lane >> 2, tg = lane & 3;
    const int r8 = lane & 7;
    const int q0 = qt * 128;
    const int t0 = q0 + w * 16 + gid;
    const int t1 = t0 + 8;

    const unsigned sbase = (unsigned)__cvta_generic_to_shared(asmem);

    const __nv_bfloat16* qbase = qb + (size_t)(b * NH + h) * TT * HD;
    unsigned qa[4][4];
    #pragma unroll
    for (int kt = 0; kt < 4; kt++) {
        qa[kt][0] = *(const unsigned*)(qbase + (size_t)t0 * HD + kt * 16 + 2 * tg);
        qa[kt][1] = *(const unsigned*)(qbase + (size_t)t1 * HD + kt * 16 + 2 * tg);
        qa[kt][2] = *(const unsigned*)(qbase + (size_t)t0 * HD + kt * 16 + 8 + 2 * tg);
        qa[kt][3] = *(const unsigned*)(qbase + (size_t)t1 * HD + kt * 16 + 8 + 2 * tg);
    }

    float oacc[8][4];
    #pragma unroll
    for (int j = 0; j < 8; j++)
        #pragma unroll
        for (int c = 0; c < 4; c++) oacc[j][c] = 0.f;
    float m0 = -1e30f, m1 = -1e30f, l0 = 0.f, l1 = 0.f;

    const int kstart = max(0, q0 - WIN + 1) & ~(ACK - 1);
    const int nch = (q0 + 128 - kstart) / ACK;

    const __nv_bfloat16* kbase = kb + (size_t)(b * KVH + kvh) * TT * HD;
    const __nv_bfloat16* vbase = vb + (size_t)(b * KVH + kvh) * TT * HD;

    auto fetch = [&](int s, int kc) {
        unsigned sk = sbase + s * ASTAGE;
        unsigned sv = sk + AOP;
        #pragma unroll
        for (int i = 0; i < 2; i++) {
            int chunk = tid + i * 256;
            int row = chunk >> 3, c = chunk & 7;
            cp16(sk + row * APITCHB + c * 16, kbase + (size_t)(kc + row) * HD + c * 8);
            cp16(sv + row * APITCHB + c * 16, vbase + (size_t)(kc + row) * HD + c * 8);
        }
    };

    unsigned koff[4], voff0;
    #pragma unroll
    for (int np = 0; np < 4; np++)
        koff[np] = (np * 16 + (lane >> 4) * 8 + r8) * APITCHB + ((lane >> 3) & 1) * 16;
    voff0 = (((lane >> 3) & 1) * 8 + r8) * APITCHB + (lane >> 4) * 16;

    fetch(0, kstart);
    asm volatile("cp.async.commit_group;\n" ::: "memory");

    for (int ci = 0; ci < nch; ci++) {
        int kc = kstart + ci * ACK;
        bool more = (ci + 1 < nch);
        if (more) {
            fetch((ci + 1) & 1, kc + ACK);
            asm volatile("cp.async.commit_group;\n" ::: "memory");
            asm volatile("cp.async.wait_group 1;\n" ::: "memory");
        } else {
            asm volatile("cp.async.wait_group 0;\n" ::: "memory");
        }
        __syncthreads();

        const unsigned sk = sbase + (ci & 1) * ASTAGE;
        const unsigned sv = sk + AOP;

        float s[8][4];
        #pragma unroll
        for (int j = 0; j < 8; j++)
            #pragma unroll
            for (int c = 0; c < 4; c++) s[j][c] = 0.f;
        #pragma unroll
        for (int ks = 0; ks < 4; ks++) {
            #pragma unroll
            for (int np = 0; np < 4; np++) {
                uint4 Bf = ldm_x4(sk + koff[np] + ks * 32);
                mma16816(s[np * 2 + 0], qa[ks][0], qa[ks][1], qa[ks][2], qa[ks][3], Bf.x, Bf.y);
                mma16816(s[np * 2 + 1], qa[ks][0], qa[ks][1], qa[ks][2], qa[ks][3], Bf.z, Bf.w);
            }
        }

        float cmax0 = -INFINITY, cmax1 = -INFINITY;
        #pragma unroll
        for (int j = 0; j < 8; j++) {
            int col = kc + j * 8 + 2 * tg;
            #pragma unroll
            for (int cc = 0; cc < 2; cc++) {
                int c0 = col + cc;
                if (!(c0 <= t0 && (t0 - c0) < WIN)) s[j][cc] = -INFINITY;
                if (!(c0 <= t1 && (t1 - c0) < WIN)) s[j][2 + cc] = -INFINITY;
            }
            cmax0 = fmaxf(cmax0, fmaxf(s[j][0], s[j][1]));
            cmax1 = fmaxf(cmax1, fmaxf(s[j][2], s[j][3]));
        }
        cmax0 = fmaxf(cmax0, __shfl_xor_sync(0xffffffffu, cmax0, 1));
        cmax0 = fmaxf(cmax0, __shfl_xor_sync(0xffffffffu, cmax0, 2));
        cmax1 = fmaxf(cmax1, __shfl_xor_sync(0xffffffffu, cmax1, 1));
        cmax1 = fmaxf(cmax1, __shfl_xor_sync(0xffffffffu, cmax1, 2));

        float nm0 = fmaxf(m0, cmax0), nm1 = fmaxf(m1, cmax1);
        float cr0 = ex2(m0 - nm0), cr1 = ex2(m1 - nm1);
        m0 = nm0; m1 = nm1;
        l0 *= cr0; l1 *= cr1;
        #pragma unroll
        for (int j = 0; j < 8; j++) {
            oacc[j][0] *= cr0; oacc[j][1] *= cr0;
            oacc[j][2] *= cr1; oacc[j][3] *= cr1;
        }
        #pragma unroll
        for (int j = 0; j < 8; j++) {
            s[j][0] = ex2(s[j][0] - nm0);
            s[j][1] = ex2(s[j][1] - nm0);
            s[j][2] = ex2(s[j][2] - nm1);
            s[j][3] = ex2(s[j][3] - nm1);
            l0 += s[j][0] + s[j][1];
            l1 += s[j][2] + s[j][3];
        }

        #pragma unroll
        for (int kt = 0; kt < 4; kt++) {
            unsigned pa0, pa1, pa2, pa3;
            {
                __nv_bfloat162 t;
                t = __floats2bfloat162_rn(s[2*kt][0],   s[2*kt][1]);   pa0 = *(unsigned*)&t;
                t = __floats2bfloat162_rn(s[2*kt][2],   s[2*kt][3]);   pa1 = *(unsigned*)&t;
                t = __floats2bfloat162_rn(s[2*kt+1][0], s[2*kt+1][1]); pa2 = *(unsigned*)&t;
                t = __floats2bfloat162_rn(s[2*kt+1][2], s[2*kt+1][3]); pa3 = *(unsigned*)&t;
            }
            #pragma unroll
            for (int dp = 0; dp < 4; dp++) {
                uint4 Vf = ldm_x4t(sv + voff0 + kt * 16 * APITCHB + dp * 32);
                mma16816(oacc[dp * 2 + 0], pa0, pa1, pa2, pa3, Vf.x, Vf.y);
                mma16816(oacc[dp * 2 + 1], pa0, pa1, pa2, pa3, Vf.z, Vf.w);
            }
        }
        __syncthreads();
    }

    l0 += __shfl_xor_sync(0xffffffffu, l0, 1);
    l0 += __shfl_xor_sync(0xffffffffu, l0, 2);
    l1 += __shfl_xor_sync(0xffffffffu, l1, 1);
    l1 += __shfl_xor_sync(0xffffffffu, l1, 2);
    float inv0 = 1.f / l0, inv1 = 1.f / l1;

    #pragma unroll
    for (int j = 0; j < 8; j++) {
        int n0 = h * HD + j * 8 + 2 * tg;
        __nv_bfloat162 p0 = __floats2bfloat162_rn(oacc[j][0] * inv0, oacc[j][1] * inv0);
        __nv_bfloat162 p1 = __floats2bfloat162_rn(oacc[j][2] * inv1, oacc[j][3] * inv1);
        *(__nv_bfloat162*)(yb + (size_t)(b * TT + t0) * (NH * HD) + n0) = p0;
        *(__nv_bfloat162*)(yb + (size_t)(b * TT + t1) * (NH * HD) + n0) = p1;
    }
}

// ---------------- launch ----------------
extern "C" void kernel_launch(void* const* d_in, const int* in_sizes, int n_in,
                              void* d_out, int out_size)
{
    const float* x            = (const float*)d_in[0];
    const float* wq           = (const float*)d_in[1];
    const float* wk           = (const float*)d_in[2];
    const float* wv           = (const float*)d_in[3];
    const float* wo           = (const float*)d_in[4];
    const float* w1           = (const float*)d_in[5];
    const float* w2           = (const float*)d_in[6];
    const float* w3           = (const float*)d_in[7];
    const float* q_norm_w     = (const float*)d_in[8];
    const float* k_norm_w     = (const float*)d_in[9];
    const float* attn_norm_w  = (const float*)d_in[10];
    const float* ffn_norm_w   = (const float*)d_in[11];
    const float* attn_scale   = (const float*)d_in[12];
    const float* ffn_scale    = (const float*)d_in[13];
    float* out = (float*)d_out;

    __nv_bfloat16 *xnb, *qkv, *qbp, *kbp, *vbp, *yb, *hnb, *gb;
    __nv_bfloat16 *wqkv, *wob, *w13, *w2b;
    float *h;
    cudaGetSymbolAddress((void**)&xnb,  g_xnb);
    cudaGetSymbolAddress((void**)&qkv,  g_qkv);
    cudaGetSymbolAddress((void**)&qbp,  g_qb);
    cudaGetSymbolAddress((void**)&kbp,  g_kb);
    cudaGetSymbolAddress((void**)&vbp,  g_vb);
    cudaGetSymbolAddress((void**)&yb,   g_yb);
    cudaGetSymbolAddress((void**)&h,    g_h);
    cudaGetSymbolAddress((void**)&hnb,  g_hnb);
    cudaGetSymbolAddress((void**)&gb,   g_gb);
    cudaGetSymbolAddress((void**)&wqkv, g_wqkv);
    cudaGetSymbolAddress((void**)&wob,  g_wob);
    cudaGetSymbolAddress((void**)&w13,  g_w13);
    cudaGetSymbolAddress((void**)&w2b,  g_w2b);

    const int M = MROWS;
    const int smem_bytes = GSMEM;
    cudaFuncSetAttribute(gemm_kernel<1>, cudaFuncAttributeMaxDynamicSharedMemorySize, smem_bytes);
    cudaFuncSetAttribute(gemm_kernel<3>, cudaFuncAttributeMaxDynamicSharedMemorySize, smem_bytes);
    cudaFuncSetAttribute(gemm_kernel<4>, cudaFuncAttributeMaxDynamicSharedMemorySize, smem_bytes);

    // 0) all weight conversions in one launch (w1/w3 interleaved)
    wconv_kernel<<<(R6 + 255) / 256, 256>>>(wq, wk, wv, wo, w1, w3, w2,
                                            wqkv, wob, w13, w2b);

    // 1) attn pre-norm
    rmsnorm_kernel<<<M, 256>>>(x, attn_norm_w, xnb, 1e-5f);

    // 2) fused QKV projection (bf16 out)
    gemm_kernel<3><<<dim3(QKVN/128, M/128), 256, smem_bytes>>>(
        xnb, wqkv, qkv, M, QKVN, DIM, nullptr, nullptr);

    // 3) fused pack q/k/v (one launch)
    const float QSCALE = 0.125f * 1.4426950408889634f;
    packall_kernel<<<(NQVEC + 2 * NKVEC) / 8, 256>>>(
        qkv, q_norm_w, k_norm_w, qbp, kbp, vbp, QSCALE);

    // 4) MMA flash attention
    fattn_kernel<<<dim3(TT / 128, BB * NH), 256>>>(qbp, kbp, vbp, yb);

    // 5) output projection + residual + layer scale -> h
    gemm_kernel<1><<<dim3(DIM/128, M/128), 256, smem_bytes>>>(
        yb, wob, h, M, DIM, NH*HD, x, attn_scale);

    // 6) ffn pre-norm
    rmsnorm_kernel<<<M, 256>>>(h, ffn_norm_w, hnb, 1e-5f);

    // 7) SwiGLU FFN: single fused w1+w3 GEMM (N=8192, interleaved), gate in epilogue
    gemm_kernel<4><<<dim3((2*HID)/128, M/128), 256, smem_bytes>>>(
        hnb, w13, gb, M, 2*HID, DIM, nullptr, nullptr);
    gemm_kernel<1><<<dim3(DIM/128, M/128), 256, smem_bytes>>>(
        gb, w2b, out, M, DIM, HID, h, ffn_scale);
}